// round 1
// baseline (speedup 1.0000x reference)
#include <cuda_runtime.h>
#include <math.h>
#include <float.h>

#define BB 8
#define EE 2048
#define DD 512
#define DA 64

// Scratch (static __device__ arrays: allocation-guard safe)
__device__ float g_q[BB * EE * DD];
__device__ float g_k[BB * EE * DD];
__device__ float g_v[BB * EE * DD];
__device__ float g_s[(size_t)BB * EE * EE];

// ---------------------------------------------------------------------------
// Kernel 1: fused QKV projection.  out = x_b @ W + bias
// grid (N/64=8, M/64=32, B*3=24), block 256.  64x64x16 tile, 4x4 per thread.
// ---------------------------------------------------------------------------
__global__ void __launch_bounds__(256) proj_kernel(
    const float* __restrict__ x,
    const float* __restrict__ Wq, const float* __restrict__ bq,
    const float* __restrict__ Wk, const float* __restrict__ bk,
    const float* __restrict__ Wv, const float* __restrict__ bv)
{
    int zb = blockIdx.z;
    int b = zb / 3, p = zb % 3;
    const float* W    = (p == 0) ? Wq : (p == 1) ? Wk : Wv;
    const float* bias = (p == 0) ? bq : (p == 1) ? bk : bv;
    float* out = ((p == 0) ? g_q : (p == 1) ? g_k : g_v) + (size_t)b * EE * DD;
    const float* A = x + (size_t)b * EE * DD;

    __shared__ float As[16][64];
    __shared__ float Bs[16][64];

    int tid = threadIdx.x;
    int m0 = blockIdx.y * 64, n0 = blockIdx.x * 64;
    int tr = tid >> 4, tc = tid & 15;
    int la_m = tid & 63, la_k = (tid >> 6) << 2;
    int lb_n = (tid & 15) << 2, lb_k = tid >> 4;

    float acc[4][4];
#pragma unroll
    for (int i = 0; i < 4; i++)
#pragma unroll
        for (int j = 0; j < 4; j++) acc[i][j] = 0.f;

    for (int k0 = 0; k0 < DD; k0 += 16) {
        float4 av = *(const float4*)(A + (size_t)(m0 + la_m) * DD + k0 + la_k);
        As[la_k + 0][la_m] = av.x; As[la_k + 1][la_m] = av.y;
        As[la_k + 2][la_m] = av.z; As[la_k + 3][la_m] = av.w;
        *(float4*)&Bs[lb_k][lb_n] =
            *(const float4*)(W + (size_t)(k0 + lb_k) * DD + n0 + lb_n);
        __syncthreads();
#pragma unroll
        for (int kk = 0; kk < 16; kk++) {
            float4 a4 = *(float4*)&As[kk][tr << 2];
            float4 b4 = *(float4*)&Bs[kk][tc << 2];
            float ar[4] = {a4.x, a4.y, a4.z, a4.w};
            float br[4] = {b4.x, b4.y, b4.z, b4.w};
#pragma unroll
            for (int i = 0; i < 4; i++)
#pragma unroll
                for (int j = 0; j < 4; j++) acc[i][j] += ar[i] * br[j];
        }
        __syncthreads();
    }

    float4 bias4 = *(const float4*)(bias + n0 + (tc << 2));
    float bb4[4] = {bias4.x, bias4.y, bias4.z, bias4.w};
#pragma unroll
    for (int i = 0; i < 4; i++) {
        float4 o;
        o.x = acc[i][0] + bb4[0];
        o.y = acc[i][1] + bb4[1];
        o.z = acc[i][2] + bb4[2];
        o.w = acc[i][3] + bb4[3];
        *(float4*)(out + (size_t)(m0 + (tr << 2) + i) * DD + n0 + (tc << 2)) = o;
    }
}

// ---------------------------------------------------------------------------
// Kernel 2: scores = q @ k^T / sqrt(D)  (+ aux GEMM, blend, adjacency mask)
// grid (E/64=32, E/64=32, B=8), block 256.
// ---------------------------------------------------------------------------
__global__ void __launch_bounds__(256) scores_kernel(
    const float* __restrict__ qa, const float* __restrict__ ka,
    const int* __restrict__ adj, const float* __restrict__ mc,
    const float* __restrict__ thr_p)
{
    int b = blockIdx.z;
    const float* Q  = g_q + (size_t)b * EE * DD;
    const float* K  = g_k + (size_t)b * EE * DD;
    const float* QA = qa + (size_t)b * EE * DA;
    const float* KA = ka + (size_t)b * EE * DA;
    float* S = g_s + (size_t)b * EE * EE;
    const int*   AD = adj + (size_t)b * EE * EE;
    const float* MC = mc  + (size_t)b * EE * EE;

    __shared__ float As[16][64];
    __shared__ float Bs[16][64];

    int tid = threadIdx.x;
    int m0 = blockIdx.y * 64, n0 = blockIdx.x * 64;   // e, f tile origins
    int tr = tid >> 4, tc = tid & 15;
    int l_r = tid & 63, l_k = (tid >> 6) << 2;        // loader: row 0..63, k 0/4/8/12

    float acc[4][4];
#pragma unroll
    for (int i = 0; i < 4; i++)
#pragma unroll
        for (int j = 0; j < 4; j++) acc[i][j] = 0.f;

    // main GEMM-NT: both operands K-contiguous
    for (int k0 = 0; k0 < DD; k0 += 16) {
        float4 av = *(const float4*)(Q + (size_t)(m0 + l_r) * DD + k0 + l_k);
        As[l_k + 0][l_r] = av.x; As[l_k + 1][l_r] = av.y;
        As[l_k + 2][l_r] = av.z; As[l_k + 3][l_r] = av.w;
        float4 bv = *(const float4*)(K + (size_t)(n0 + l_r) * DD + k0 + l_k);
        Bs[l_k + 0][l_r] = bv.x; Bs[l_k + 1][l_r] = bv.y;
        Bs[l_k + 2][l_r] = bv.z; Bs[l_k + 3][l_r] = bv.w;
        __syncthreads();
#pragma unroll
        for (int kk = 0; kk < 16; kk++) {
            float4 a4 = *(float4*)&As[kk][tr << 2];
            float4 b4 = *(float4*)&Bs[kk][tc << 2];
            float ar[4] = {a4.x, a4.y, a4.z, a4.w};
            float br[4] = {b4.x, b4.y, b4.z, b4.w};
#pragma unroll
            for (int i = 0; i < 4; i++)
#pragma unroll
                for (int j = 0; j < 4; j++) acc[i][j] += ar[i] * br[j];
        }
        __syncthreads();
    }

    // aux GEMM-NT over DA=64
    float acc2[4][4];
#pragma unroll
    for (int i = 0; i < 4; i++)
#pragma unroll
        for (int j = 0; j < 4; j++) acc2[i][j] = 0.f;

    for (int k0 = 0; k0 < DA; k0 += 16) {
        float4 av = *(const float4*)(QA + (size_t)(m0 + l_r) * DA + k0 + l_k);
        As[l_k + 0][l_r] = av.x; As[l_k + 1][l_r] = av.y;
        As[l_k + 2][l_r] = av.z; As[l_k + 3][l_r] = av.w;
        float4 bv = *(const float4*)(KA + (size_t)(n0 + l_r) * DA + k0 + l_k);
        Bs[l_k + 0][l_r] = bv.x; Bs[l_k + 1][l_r] = bv.y;
        Bs[l_k + 2][l_r] = bv.z; Bs[l_k + 3][l_r] = bv.w;
        __syncthreads();
#pragma unroll
        for (int kk = 0; kk < 16; kk++) {
            float4 a4 = *(float4*)&As[kk][tr << 2];
            float4 b4 = *(float4*)&Bs[kk][tc << 2];
            float ar[4] = {a4.x, a4.y, a4.z, a4.w};
            float br[4] = {b4.x, b4.y, b4.z, b4.w};
#pragma unroll
            for (int i = 0; i < 4; i++)
#pragma unroll
                for (int j = 0; j < 4; j++) acc2[i][j] += ar[i] * br[j];
        }
        __syncthreads();
    }

    // epilogue: scale, blend under merge mask, adjacency mask, store
    float thr = *thr_p;
    float sq  = sqrtf((float)DD);   // 22.627417 (constant-folded)
#pragma unroll
    for (int i = 0; i < 4; i++) {
        int e = m0 + (tr << 2) + i;
        int f = n0 + (tc << 2);
        int4   ad = *(const int4*)(AD + (size_t)e * EE + f);
        float4 cc = *(const float4*)(MC + (size_t)e * EE + f);
        int   adr[4] = {ad.x, ad.y, ad.z, ad.w};
        float ccr[4] = {cc.x, cc.y, cc.z, cc.w};
        float4 o;
        float outr[4];
#pragma unroll
        for (int j = 0; j < 4; j++) {
            float s  = acc[i][j] / sq;
            float sa = acc2[i][j] * 0.125f;   // / sqrt(64), exact
            bool merge = (s > thr) && (sa != 0.0f);
            float c = ccr[j];
            float blended = (1.0f - c) * s + c * sa;
            float r = merge ? blended : s;
            if (adr[j] == 0) r = -FLT_MAX;    // finfo(f32).min
            outr[j] = r;
        }
        o.x = outr[0]; o.y = outr[1]; o.z = outr[2]; o.w = outr[3];
        *(float4*)(S + (size_t)e * EE + f) = o;
    }
}

// ---------------------------------------------------------------------------
// Kernel 3: row softmax over last axis (row length 2048). 1 block per row.
// ---------------------------------------------------------------------------
__global__ void __launch_bounds__(256) softmax_kernel()
{
    size_t row = blockIdx.x;
    float* S = g_s + row * EE;
    int tid = threadIdx.x;

    float v[8];
    float m = -FLT_MAX;
#pragma unroll
    for (int i = 0; i < 8; i++) {
        v[i] = S[tid + i * 256];
        m = fmaxf(m, v[i]);
    }
    __shared__ float redm[8];
    __shared__ float reds[8];
#pragma unroll
    for (int o = 16; o > 0; o >>= 1) m = fmaxf(m, __shfl_xor_sync(~0u, m, o));
    if ((tid & 31) == 0) redm[tid >> 5] = m;
    __syncthreads();
#pragma unroll
    for (int i = 0; i < 8; i++) m = fmaxf(m, redm[i]);

    float s = 0.f;
#pragma unroll
    for (int i = 0; i < 8; i++) {
        v[i] = expf(v[i] - m);
        s += v[i];
    }
#pragma unroll
    for (int o = 16; o > 0; o >>= 1) s += __shfl_xor_sync(~0u, s, o);
    if ((tid & 31) == 0) reds[tid >> 5] = s;
    __syncthreads();
    s = 0.f;
#pragma unroll
    for (int i = 0; i < 8; i++) s += reds[i];

    float inv = 1.0f / s;
#pragma unroll
    for (int i = 0; i < 8; i++) S[tid + i * 256] = v[i] * inv;
}

// ---------------------------------------------------------------------------
// Kernel 4: out = attn @ v.  M=2048, N=512, K=2048.  GEMM-NN.
// grid (8, 32, 8), block 256.
// ---------------------------------------------------------------------------
__global__ void __launch_bounds__(256) av_kernel(float* __restrict__ out)
{
    int b = blockIdx.z;
    const float* A  = g_s + (size_t)b * EE * EE;   // probs, row stride EE
    const float* Bv = g_v + (size_t)b * EE * DD;   // row stride DD
    float* C = out + (size_t)b * EE * DD;

    __shared__ float As[16][64];
    __shared__ float Bs[16][64];

    int tid = threadIdx.x;
    int m0 = blockIdx.y * 64, n0 = blockIdx.x * 64;
    int tr = tid >> 4, tc = tid & 15;
    int la_m = tid & 63, la_k = (tid >> 6) << 2;
    int lb_n = (tid & 15) << 2, lb_k = tid >> 4;

    float acc[4][4];
#pragma unroll
    for (int i = 0; i < 4; i++)
#pragma unroll
        for (int j = 0; j < 4; j++) acc[i][j] = 0.f;

    for (int k0 = 0; k0 < EE; k0 += 16) {
        float4 av = *(const float4*)(A + (size_t)(m0 + la_m) * EE + k0 + la_k);
        As[la_k + 0][la_m] = av.x; As[la_k + 1][la_m] = av.y;
        As[la_k + 2][la_m] = av.z; As[la_k + 3][la_m] = av.w;
        *(float4*)&Bs[lb_k][lb_n] =
            *(const float4*)(Bv + (size_t)(k0 + lb_k) * DD + n0 + lb_n);
        __syncthreads();
#pragma unroll
        for (int kk = 0; kk < 16; kk++) {
            float4 a4 = *(float4*)&As[kk][tr << 2];
            float4 b4 = *(float4*)&Bs[kk][tc << 2];
            float ar[4] = {a4.x, a4.y, a4.z, a4.w};
            float br[4] = {b4.x, b4.y, b4.z, b4.w};
#pragma unroll
            for (int i = 0; i < 4; i++)
#pragma unroll
                for (int j = 0; j < 4; j++) acc[i][j] += ar[i] * br[j];
        }
        __syncthreads();
    }

#pragma unroll
    for (int i = 0; i < 4; i++) {
        float4 o;
        o.x = acc[i][0]; o.y = acc[i][1]; o.z = acc[i][2]; o.w = acc[i][3];
        *(float4*)(C + (size_t)(m0 + (tr << 2) + i) * DD + n0 + (tc << 2)) = o;
    }
}

// ---------------------------------------------------------------------------
extern "C" void kernel_launch(void* const* d_in, const int* in_sizes, int n_in,
                              void* d_out, int out_size)
{
    const float* x   = (const float*)d_in[0];
    const float* qa  = (const float*)d_in[1];
    const float* ka  = (const float*)d_in[2];
    const int*   adj = (const int*)  d_in[3];
    const float* mc  = (const float*)d_in[4];
    const float* Wq  = (const float*)d_in[5];
    const float* bq  = (const float*)d_in[6];
    const float* Wk  = (const float*)d_in[7];
    const float* bk  = (const float*)d_in[8];
    const float* Wv  = (const float*)d_in[9];
    const float* bv  = (const float*)d_in[10];
    const float* thr = (const float*)d_in[11];

    dim3 blk(256);
    proj_kernel<<<dim3(DD / 64, EE / 64, BB * 3), blk>>>(x, Wq, bq, Wk, bk, Wv, bv);
    scores_kernel<<<dim3(EE / 64, EE / 64, BB), blk>>>(qa, ka, adj, mc, thr);
    softmax_kernel<<<BB * EE, 256>>>();
    av_kernel<<<dim3(DD / 64, EE / 64, BB), blk>>>((float*)d_out);
}

// round 2
// speedup vs baseline: 1.5087x; 1.5087x over previous
#include <cuda_runtime.h>
#include <math.h>
#include <float.h>

#define BB 8
#define EE 2048
#define DD 512
#define DA 64

typedef unsigned long long ull;

// Scratch (static __device__ arrays: allocation-guard safe)
__device__ float g_q[BB * EE * DD];
__device__ float g_k[BB * EE * DD];
__device__ float g_v[BB * EE * DD];
__device__ float g_s[(size_t)BB * EE * EE];

// ---------------------------------------------------------------------------
// packed f32x2 helpers
// ---------------------------------------------------------------------------
__device__ __forceinline__ ull pk2(float lo, float hi) {
    ull r;
    asm("mov.b64 %0, {%1,%2};" : "=l"(r) : "f"(lo), "f"(hi));
    return r;
}
__device__ __forceinline__ void ffma2(ull& c, ull a, ull b) {
    asm("fma.rn.f32x2 %0, %1, %2, %0;" : "+l"(c) : "l"(a), "l"(b));
}
__device__ __forceinline__ float2 upk2(ull v) {
    float2 f;
    asm("mov.b64 {%0,%1}, %2;" : "=f"(f.x), "=f"(f.y) : "l"(v));
    return f;
}

// ---------------------------------------------------------------------------
// 128x128 tile GEMM core, 8x8 per thread (2x2 quadrants of 4x4), f32x2 FMA.
// A: row-major M x K (caller pre-offsets to tile row m0), lda = K stride.
// B: if BT, row-major N x K (caller offsets to n0 row); else row-major K x N
//    (caller offsets to n0 column).
// acc[i][j]: i = 8 rows (2 quadrants of 4), j = 4 col-pairs (2 quadrants of 2).
// ---------------------------------------------------------------------------
template <bool BT>
__device__ __forceinline__ void mm_tile(
    const float* __restrict__ A, int lda,
    const float* __restrict__ B, int ldb,
    int Ktot, float (*As)[128], float (*Bs)[128], ull acc[8][4])
{
    const int t = threadIdx.x;
    const int a_c4 = (t & 3) << 2;   // k offset within chunk: 0,4,8,12
    const int a_r  = t >> 2;         // 0..63 (rows a_r and a_r+64)
    const int b_n4 = (t & 31) << 2;  // 0..124
    const int b_k  = t >> 5;         // 0..7 (rows b_k and b_k+8)
    const int tx = t & 15, ty = t >> 4;

    for (int k0 = 0; k0 < Ktot; k0 += 16) {
        float4 va0 = *(const float4*)(A + (size_t)a_r * lda + k0 + a_c4);
        float4 va1 = *(const float4*)(A + (size_t)(a_r + 64) * lda + k0 + a_c4);
        As[a_c4 + 0][a_r] = va0.x; As[a_c4 + 1][a_r] = va0.y;
        As[a_c4 + 2][a_r] = va0.z; As[a_c4 + 3][a_r] = va0.w;
        As[a_c4 + 0][a_r + 64] = va1.x; As[a_c4 + 1][a_r + 64] = va1.y;
        As[a_c4 + 2][a_r + 64] = va1.z; As[a_c4 + 3][a_r + 64] = va1.w;
        if (BT) {
            float4 vb0 = *(const float4*)(B + (size_t)a_r * ldb + k0 + a_c4);
            float4 vb1 = *(const float4*)(B + (size_t)(a_r + 64) * ldb + k0 + a_c4);
            Bs[a_c4 + 0][a_r] = vb0.x; Bs[a_c4 + 1][a_r] = vb0.y;
            Bs[a_c4 + 2][a_r] = vb0.z; Bs[a_c4 + 3][a_r] = vb0.w;
            Bs[a_c4 + 0][a_r + 64] = vb1.x; Bs[a_c4 + 1][a_r + 64] = vb1.y;
            Bs[a_c4 + 2][a_r + 64] = vb1.z; Bs[a_c4 + 3][a_r + 64] = vb1.w;
        } else {
            *(float4*)&Bs[b_k][b_n4] =
                *(const float4*)(B + (size_t)(k0 + b_k) * ldb + b_n4);
            *(float4*)&Bs[b_k + 8][b_n4] =
                *(const float4*)(B + (size_t)(k0 + b_k + 8) * ldb + b_n4);
        }
        __syncthreads();
#pragma unroll
        for (int kk = 0; kk < 16; kk++) {
            float4 a0 = *(float4*)&As[kk][ty << 2];
            float4 a1 = *(float4*)&As[kk][64 + (ty << 2)];
            float4 b0 = *(float4*)&Bs[kk][tx << 2];
            float4 b1 = *(float4*)&Bs[kk][64 + (tx << 2)];
            ull bb[4] = {pk2(b0.x, b0.y), pk2(b0.z, b0.w),
                         pk2(b1.x, b1.y), pk2(b1.z, b1.w)};
            float aa[8] = {a0.x, a0.y, a0.z, a0.w, a1.x, a1.y, a1.z, a1.w};
#pragma unroll
            for (int i = 0; i < 8; i++) {
                ull ai = pk2(aa[i], aa[i]);
#pragma unroll
                for (int j = 0; j < 4; j++) ffma2(acc[i][j], ai, bb[j]);
            }
        }
        __syncthreads();
    }
}

// row index inside 128 tile for acc row i
__device__ __forceinline__ int tile_row(int i, int ty) {
    return ((i >> 2) << 6) + (ty << 2) + (i & 3);
}

// ---------------------------------------------------------------------------
// Kernel 1: fused QKV projection. grid (512/128=4, 2048/128=16, 24), 256 thr.
// ---------------------------------------------------------------------------
__global__ void __launch_bounds__(256) proj_kernel(
    const float* __restrict__ x,
    const float* __restrict__ Wq, const float* __restrict__ bq,
    const float* __restrict__ Wk, const float* __restrict__ bk,
    const float* __restrict__ Wv, const float* __restrict__ bv)
{
    __shared__ __align__(16) float As[16][128];
    __shared__ __align__(16) float Bs[16][128];

    int zb = blockIdx.z;
    int b = zb / 3, p = zb % 3;
    const float* W    = (p == 0) ? Wq : (p == 1) ? Wk : Wv;
    const float* bias = (p == 0) ? bq : (p == 1) ? bk : bv;
    float* out = ((p == 0) ? g_q : (p == 1) ? g_k : g_v) + (size_t)b * EE * DD;

    int m0 = blockIdx.y * 128, n0 = blockIdx.x * 128;
    const float* A = x + (size_t)b * EE * DD + (size_t)m0 * DD;
    const float* Bm = W + n0;

    ull acc[8][4];
#pragma unroll
    for (int i = 0; i < 8; i++)
#pragma unroll
        for (int j = 0; j < 4; j++) acc[i][j] = pk2(0.f, 0.f);

    mm_tile<false>(A, DD, Bm, DD, DD, As, Bs, acc);

    int tx = threadIdx.x & 15, ty = threadIdx.x >> 4;
    float4 bias0 = *(const float4*)(bias + n0 + (tx << 2));
    float4 bias1 = *(const float4*)(bias + n0 + 64 + (tx << 2));
#pragma unroll
    for (int i = 0; i < 8; i++) {
        int m = m0 + tile_row(i, ty);
        float2 c0 = upk2(acc[i][0]), c1 = upk2(acc[i][1]);
        float2 c2 = upk2(acc[i][2]), c3 = upk2(acc[i][3]);
        float4 o0 = {c0.x + bias0.x, c0.y + bias0.y, c1.x + bias0.z, c1.y + bias0.w};
        float4 o1 = {c2.x + bias1.x, c2.y + bias1.y, c3.x + bias1.z, c3.y + bias1.w};
        *(float4*)(out + (size_t)m * DD + n0 + (tx << 2)) = o0;
        *(float4*)(out + (size_t)m * DD + n0 + 64 + (tx << 2)) = o1;
    }
}

// ---------------------------------------------------------------------------
// Kernel 2: scores. grid (16, 16, 8), 256 thr. Main GEMM-NT K=512 + aux
// GEMM-NT K=64, blend + adjacency mask epilogue.
// ---------------------------------------------------------------------------
__global__ void __launch_bounds__(256) scores_kernel(
    const float* __restrict__ qa, const float* __restrict__ ka,
    const int* __restrict__ adj, const float* __restrict__ mc,
    const float* __restrict__ thr_p)
{
    __shared__ __align__(16) float As[16][128];
    __shared__ __align__(16) float Bs[16][128];

    int b = blockIdx.z;
    int m0 = blockIdx.y * 128, n0 = blockIdx.x * 128;

    ull acc[8][4], acc2[8][4];
#pragma unroll
    for (int i = 0; i < 8; i++)
#pragma unroll
        for (int j = 0; j < 4; j++) { acc[i][j] = pk2(0.f, 0.f); acc2[i][j] = pk2(0.f, 0.f); }

    // main: Q (m rows) x K^T (n rows), both K-contiguous
    mm_tile<true>(g_q + (size_t)b * EE * DD + (size_t)m0 * DD, DD,
                  g_k + (size_t)b * EE * DD + (size_t)n0 * DD, DD,
                  DD, As, Bs, acc);
    // aux: QA x KA^T over DA=64
    mm_tile<true>(qa + (size_t)b * EE * DA + (size_t)m0 * DA, DA,
                  ka + (size_t)b * EE * DA + (size_t)n0 * DA, DA,
                  DA, As, Bs, acc2);

    float* S = g_s + (size_t)b * EE * EE;
    const int*   AD = adj + (size_t)b * EE * EE;
    const float* MC = mc  + (size_t)b * EE * EE;
    float thr = *thr_p;
    const float inv_sq = 1.0f / 22.627416997969522f;  // 1/sqrt(512)

    int tx = threadIdx.x & 15, ty = threadIdx.x >> 4;
#pragma unroll
    for (int i = 0; i < 8; i++) {
        int e = m0 + tile_row(i, ty);
#pragma unroll
        for (int half = 0; half < 2; half++) {
            int f = n0 + half * 64 + (tx << 2);
            int4   ad = *(const int4*)(AD + (size_t)e * EE + f);
            float4 cc = *(const float4*)(MC + (size_t)e * EE + f);
            float2 sA = upk2(acc[i][half * 2]);
            float2 sB = upk2(acc[i][half * 2 + 1]);
            float2 aA = upk2(acc2[i][half * 2]);
            float2 aB = upk2(acc2[i][half * 2 + 1]);
            float sv[4]  = {sA.x, sA.y, sB.x, sB.y};
            float sav[4] = {aA.x, aA.y, aB.x, aB.y};
            int   adr[4] = {ad.x, ad.y, ad.z, ad.w};
            float ccr[4] = {cc.x, cc.y, cc.z, cc.w};
            float outr[4];
#pragma unroll
            for (int j = 0; j < 4; j++) {
                float s  = sv[j] * inv_sq;
                float sa = sav[j] * 0.125f;     // 1/sqrt(64), exact
                bool merge = (s > thr) && (sa != 0.0f);
                float c = ccr[j];
                float r = merge ? (1.0f - c) * s + c * sa : s;
                if (adr[j] == 0) r = -FLT_MAX;
                outr[j] = r;
            }
            float4 o = {outr[0], outr[1], outr[2], outr[3]};
            *(float4*)(S + (size_t)e * EE + f) = o;
        }
    }
}

// ---------------------------------------------------------------------------
// Kernel 3: row softmax, one block per row of length 2048.
// ---------------------------------------------------------------------------
__global__ void __launch_bounds__(256) softmax_kernel()
{
    size_t row = blockIdx.x;
    float* S = g_s + row * EE;
    int tid = threadIdx.x;

    float v[8];
    float m = -FLT_MAX;
#pragma unroll
    for (int i = 0; i < 8; i++) {
        v[i] = S[tid + i * 256];
        m = fmaxf(m, v[i]);
    }
    __shared__ float redm[8];
    __shared__ float reds[8];
#pragma unroll
    for (int o = 16; o > 0; o >>= 1) m = fmaxf(m, __shfl_xor_sync(~0u, m, o));
    if ((tid & 31) == 0) redm[tid >> 5] = m;
    __syncthreads();
#pragma unroll
    for (int i = 0; i < 8; i++) m = fmaxf(m, redm[i]);

    float s = 0.f;
#pragma unroll
    for (int i = 0; i < 8; i++) {
        v[i] = expf(v[i] - m);
        s += v[i];
    }
#pragma unroll
    for (int o = 16; o > 0; o >>= 1) s += __shfl_xor_sync(~0u, s, o);
    if ((tid & 31) == 0) reds[tid >> 5] = s;
    __syncthreads();
    s = 0.f;
#pragma unroll
    for (int i = 0; i < 8; i++) s += reds[i];

    float inv = 1.0f / s;
#pragma unroll
    for (int i = 0; i < 8; i++) S[tid + i * 256] = v[i] * inv;
}

// ---------------------------------------------------------------------------
// Kernel 4: out = attn @ v. grid (4, 16, 8), 256 thr. GEMM-NN K=2048.
// ---------------------------------------------------------------------------
__global__ void __launch_bounds__(256) av_kernel(float* __restrict__ out)
{
    __shared__ __align__(16) float As[16][128];
    __shared__ __align__(16) float Bs[16][128];

    int b = blockIdx.z;
    int m0 = blockIdx.y * 128, n0 = blockIdx.x * 128;
    const float* A  = g_s + (size_t)b * EE * EE + (size_t)m0 * EE;
    const float* Bv = g_v + (size_t)b * EE * DD + n0;
    float* C = out + (size_t)b * EE * DD;

    ull acc[8][4];
#pragma unroll
    for (int i = 0; i < 8; i++)
#pragma unroll
        for (int j = 0; j < 4; j++) acc[i][j] = pk2(0.f, 0.f);

    mm_tile<false>(A, EE, Bv, DD, EE, As, Bs, acc);

    int tx = threadIdx.x & 15, ty = threadIdx.x >> 4;
#pragma unroll
    for (int i = 0; i < 8; i++) {
        int m = m0 + tile_row(i, ty);
        float2 c0 = upk2(acc[i][0]), c1 = upk2(acc[i][1]);
        float2 c2 = upk2(acc[i][2]), c3 = upk2(acc[i][3]);
        float4 o0 = {c0.x, c0.y, c1.x, c1.y};
        float4 o1 = {c2.x, c2.y, c3.x, c3.y};
        *(float4*)(C + (size_t)m * DD + n0 + (tx << 2)) = o0;
        *(float4*)(C + (size_t)m * DD + n0 + 64 + (tx << 2)) = o1;
    }
}

// ---------------------------------------------------------------------------
extern "C" void kernel_launch(void* const* d_in, const int* in_sizes, int n_in,
                              void* d_out, int out_size)
{
    const float* x   = (const float*)d_in[0];
    const float* qa  = (const float*)d_in[1];
    const float* ka  = (const float*)d_in[2];
    const int*   adj = (const int*)  d_in[3];
    const float* mc  = (const float*)d_in[4];
    const float* Wq  = (const float*)d_in[5];
    const float* bq  = (const float*)d_in[6];
    const float* Wk  = (const float*)d_in[7];
    const float* bk  = (const float*)d_in[8];
    const float* Wv  = (const float*)d_in[9];
    const float* bv  = (const float*)d_in[10];
    const float* thr = (const float*)d_in[11];

    dim3 blk(256);
    proj_kernel<<<dim3(DD / 128, EE / 128, BB * 3), blk>>>(x, Wq, bq, Wk, bk, Wv, bv);
    scores_kernel<<<dim3(EE / 128, EE / 128, BB), blk>>>(qa, ka, adj, mc, thr);
    softmax_kernel<<<BB * EE, 256>>>();
    av_kernel<<<dim3(DD / 128, EE / 128, BB), blk>>>((float*)d_out);
}

// round 3
// speedup vs baseline: 1.6603x; 1.1005x over previous
#include <cuda_runtime.h>
#include <math.h>
#include <float.h>

#define BB 8
#define EE 2048
#define DD 512
#define DA 64

typedef unsigned long long ull;

// Scratch (static __device__ arrays: allocation-guard safe)
__device__ float g_q[BB * EE * DD];
__device__ float g_k[BB * EE * DD];
__device__ float g_v[BB * EE * DD];
__device__ float g_s[(size_t)BB * EE * EE];

// ---------------------------------------------------------------------------
// packed f32x2 helpers
// ---------------------------------------------------------------------------
__device__ __forceinline__ ull pk2(float lo, float hi) {
    ull r;
    asm("mov.b64 %0, {%1,%2};" : "=l"(r) : "f"(lo), "f"(hi));
    return r;
}
__device__ __forceinline__ void ffma2(ull& c, ull a, ull b) {
    asm("fma.rn.f32x2 %0, %1, %2, %0;" : "+l"(c) : "l"(a), "l"(b));
}
__device__ __forceinline__ float2 upk2(ull v) {
    float2 f;
    asm("mov.b64 {%0,%1}, %2;" : "=f"(f.x), "=f"(f.y) : "l"(v));
    return f;
}

// ---------------------------------------------------------------------------
// 128x128 tile GEMM core, 8x8 per thread, f32x2 FMA, double-buffered smem.
// acc[rp][j]: rp = 4 row-pairs (rows packed in the f32x2 lanes), j = 8 cols.
//   rp0=(ty*4+0, ty*4+1) rp1=(ty*4+2, ty*4+3) rp2/rp3 = same +64.
//   j 0..3 -> col tx*4+j ; j 4..7 -> col 64+tx*4+(j-4)
// ---------------------------------------------------------------------------
template <bool BT>
__device__ __forceinline__ void mm_tile(
    const float* __restrict__ A, int lda,
    const float* __restrict__ B, int ldb,
    int Ktot, float (*As)[16][128], float (*Bs)[16][128], ull acc[4][8])
{
    const int t = threadIdx.x;
    const int a_c4 = (t & 3) << 2;   // k offset within chunk: 0,4,8,12
    const int a_r  = t >> 2;         // 0..63 (rows a_r and a_r+64)
    const int b_n4 = (t & 31) << 2;  // 0..124
    const int b_k  = t >> 5;         // 0..7
    const int tx = t & 15, ty = t >> 4;

    float4 ra0, ra1, rb0, rb1;

    // prologue: load k0 = 0
    ra0 = *(const float4*)(A + (size_t)a_r * lda + a_c4);
    ra1 = *(const float4*)(A + (size_t)(a_r + 64) * lda + a_c4);
    if (BT) {
        rb0 = *(const float4*)(B + (size_t)a_r * ldb + a_c4);
        rb1 = *(const float4*)(B + (size_t)(a_r + 64) * ldb + a_c4);
    } else {
        rb0 = *(const float4*)(B + (size_t)b_k * ldb + b_n4);
        rb1 = *(const float4*)(B + (size_t)(b_k + 8) * ldb + b_n4);
    }

    int buf = 0;
    // store prologue tile into buffer 0
    {
        As[0][a_c4 + 0][a_r] = ra0.x; As[0][a_c4 + 1][a_r] = ra0.y;
        As[0][a_c4 + 2][a_r] = ra0.z; As[0][a_c4 + 3][a_r] = ra0.w;
        As[0][a_c4 + 0][a_r + 64] = ra1.x; As[0][a_c4 + 1][a_r + 64] = ra1.y;
        As[0][a_c4 + 2][a_r + 64] = ra1.z; As[0][a_c4 + 3][a_r + 64] = ra1.w;
        if (BT) {
            Bs[0][a_c4 + 0][a_r] = rb0.x; Bs[0][a_c4 + 1][a_r] = rb0.y;
            Bs[0][a_c4 + 2][a_r] = rb0.z; Bs[0][a_c4 + 3][a_r] = rb0.w;
            Bs[0][a_c4 + 0][a_r + 64] = rb1.x; Bs[0][a_c4 + 1][a_r + 64] = rb1.y;
            Bs[0][a_c4 + 2][a_r + 64] = rb1.z; Bs[0][a_c4 + 3][a_r + 64] = rb1.w;
        } else {
            *(float4*)&Bs[0][b_k][b_n4] = rb0;
            *(float4*)&Bs[0][b_k + 8][b_n4] = rb1;
        }
    }
    __syncthreads();

    for (int k0 = 0; k0 < Ktot; k0 += 16) {
        const bool more = (k0 + 16) < Ktot;
        if (more) {
            int kn = k0 + 16;
            ra0 = *(const float4*)(A + (size_t)a_r * lda + kn + a_c4);
            ra1 = *(const float4*)(A + (size_t)(a_r + 64) * lda + kn + a_c4);
            if (BT) {
                rb0 = *(const float4*)(B + (size_t)a_r * ldb + kn + a_c4);
                rb1 = *(const float4*)(B + (size_t)(a_r + 64) * ldb + kn + a_c4);
            } else {
                rb0 = *(const float4*)(B + (size_t)(kn + b_k) * ldb + b_n4);
                rb1 = *(const float4*)(B + (size_t)(kn + b_k + 8) * ldb + b_n4);
            }
        }
#pragma unroll
        for (int kk = 0; kk < 16; kk++) {
            ulonglong2 ap0 = *(const ulonglong2*)&As[buf][kk][ty << 2];
            ulonglong2 ap1 = *(const ulonglong2*)&As[buf][kk][64 + (ty << 2)];
            float4 b0 = *(const float4*)&Bs[buf][kk][tx << 2];
            float4 b1 = *(const float4*)&Bs[buf][kk][64 + (tx << 2)];
            ull bb[8] = {pk2(b0.x, b0.x), pk2(b0.y, b0.y),
                         pk2(b0.z, b0.z), pk2(b0.w, b0.w),
                         pk2(b1.x, b1.x), pk2(b1.y, b1.y),
                         pk2(b1.z, b1.z), pk2(b1.w, b1.w)};
            ull aa[4] = {ap0.x, ap0.y, ap1.x, ap1.y};
#pragma unroll
            for (int rp = 0; rp < 4; rp++)
#pragma unroll
                for (int j = 0; j < 8; j++) ffma2(acc[rp][j], aa[rp], bb[j]);
        }
        if (more) {
            int nb = buf ^ 1;
            As[nb][a_c4 + 0][a_r] = ra0.x; As[nb][a_c4 + 1][a_r] = ra0.y;
            As[nb][a_c4 + 2][a_r] = ra0.z; As[nb][a_c4 + 3][a_r] = ra0.w;
            As[nb][a_c4 + 0][a_r + 64] = ra1.x; As[nb][a_c4 + 1][a_r + 64] = ra1.y;
            As[nb][a_c4 + 2][a_r + 64] = ra1.z; As[nb][a_c4 + 3][a_r + 64] = ra1.w;
            if (BT) {
                Bs[nb][a_c4 + 0][a_r] = rb0.x; Bs[nb][a_c4 + 1][a_r] = rb0.y;
                Bs[nb][a_c4 + 2][a_r] = rb0.z; Bs[nb][a_c4 + 3][a_r] = rb0.w;
                Bs[nb][a_c4 + 0][a_r + 64] = rb1.x; Bs[nb][a_c4 + 1][a_r + 64] = rb1.y;
                Bs[nb][a_c4 + 2][a_r + 64] = rb1.z; Bs[nb][a_c4 + 3][a_r + 64] = rb1.w;
            } else {
                *(float4*)&Bs[nb][b_k][b_n4] = rb0;
                *(float4*)&Bs[nb][b_k + 8][b_n4] = rb1;
            }
        }
        __syncthreads();
        buf ^= 1;
    }
}

// row base inside 128 tile for acc row-pair rp
__device__ __forceinline__ int pair_row(int rp, int ty) {
    return ((rp >> 1) << 6) + (ty << 2) + ((rp & 1) << 1);
}

// ---------------------------------------------------------------------------
// Kernel 1: fused QKV projection. grid (4, 16, 24), 256 thr.
// ---------------------------------------------------------------------------
__global__ void __launch_bounds__(256, 2) proj_kernel(
    const float* __restrict__ x,
    const float* __restrict__ Wq, const float* __restrict__ bq,
    const float* __restrict__ Wk, const float* __restrict__ bk,
    const float* __restrict__ Wv, const float* __restrict__ bv)
{
    __shared__ __align__(16) float As[2][16][128];
    __shared__ __align__(16) float Bs[2][16][128];

    int zb = blockIdx.z;
    int b = zb / 3, p = zb % 3;
    const float* W    = (p == 0) ? Wq : (p == 1) ? Wk : Wv;
    const float* bias = (p == 0) ? bq : (p == 1) ? bk : bv;
    float* out = ((p == 0) ? g_q : (p == 1) ? g_k : g_v) + (size_t)b * EE * DD;

    int m0 = blockIdx.y * 128, n0 = blockIdx.x * 128;

    ull acc[4][8];
#pragma unroll
    for (int i = 0; i < 4; i++)
#pragma unroll
        for (int j = 0; j < 8; j++) acc[i][j] = 0ull;

    mm_tile<false>(x + (size_t)b * EE * DD + (size_t)m0 * DD, DD,
                   W + n0, DD, DD, As, Bs, acc);

    int tx = threadIdx.x & 15, ty = threadIdx.x >> 4;
    float4 bias0 = *(const float4*)(bias + n0 + (tx << 2));
    float4 bias1 = *(const float4*)(bias + n0 + 64 + (tx << 2));
    float bb0[4] = {bias0.x, bias0.y, bias0.z, bias0.w};
    float bb1[4] = {bias1.x, bias1.y, bias1.z, bias1.w};
#pragma unroll
    for (int rp = 0; rp < 4; rp++) {
        int r = m0 + pair_row(rp, ty);
        float2 c[8];
#pragma unroll
        for (int j = 0; j < 8; j++) c[j] = upk2(acc[rp][j]);
        float4 lo0 = {c[0].x + bb0[0], c[1].x + bb0[1], c[2].x + bb0[2], c[3].x + bb0[3]};
        float4 lo1 = {c[4].x + bb1[0], c[5].x + bb1[1], c[6].x + bb1[2], c[7].x + bb1[3]};
        float4 hi0 = {c[0].y + bb0[0], c[1].y + bb0[1], c[2].y + bb0[2], c[3].y + bb0[3]};
        float4 hi1 = {c[4].y + bb1[0], c[5].y + bb1[1], c[6].y + bb1[2], c[7].y + bb1[3]};
        *(float4*)(out + (size_t)r * DD + n0 + (tx << 2)) = lo0;
        *(float4*)(out + (size_t)r * DD + n0 + 64 + (tx << 2)) = lo1;
        *(float4*)(out + (size_t)(r + 1) * DD + n0 + (tx << 2)) = hi0;
        *(float4*)(out + (size_t)(r + 1) * DD + n0 + 64 + (tx << 2)) = hi1;
    }
}

// ---------------------------------------------------------------------------
// Kernel 2: scores. grid (16, 16, 8), 256 thr.
// ---------------------------------------------------------------------------
__global__ void __launch_bounds__(256, 2) scores_kernel(
    const float* __restrict__ qa, const float* __restrict__ ka,
    const int* __restrict__ adj, const float* __restrict__ mc,
    const float* __restrict__ thr_p)
{
    __shared__ __align__(16) float As[2][16][128];
    __shared__ __align__(16) float Bs[2][16][128];

    int b = blockIdx.z;
    int m0 = blockIdx.y * 128, n0 = blockIdx.x * 128;

    ull acc[4][8], acc2[4][8];
#pragma unroll
    for (int i = 0; i < 4; i++)
#pragma unroll
        for (int j = 0; j < 8; j++) { acc[i][j] = 0ull; acc2[i][j] = 0ull; }

    mm_tile<true>(g_q + (size_t)b * EE * DD + (size_t)m0 * DD, DD,
                  g_k + (size_t)b * EE * DD + (size_t)n0 * DD, DD,
                  DD, As, Bs, acc);
    mm_tile<true>(qa + (size_t)b * EE * DA + (size_t)m0 * DA, DA,
                  ka + (size_t)b * EE * DA + (size_t)n0 * DA, DA,
                  DA, As, Bs, acc2);

    float* S = g_s + (size_t)b * EE * EE;
    const int*   AD = adj + (size_t)b * EE * EE;
    const float* MC = mc  + (size_t)b * EE * EE;
    float thr = *thr_p;
    const float inv_sq = 1.0f / 22.627416997969522f;  // 1/sqrt(512)

    int tx = threadIdx.x & 15, ty = threadIdx.x >> 4;
#pragma unroll
    for (int rp = 0; rp < 4; rp++) {
        int rbase = m0 + pair_row(rp, ty);
        float2 c[8], c2[8];
#pragma unroll
        for (int j = 0; j < 8; j++) { c[j] = upk2(acc[rp][j]); c2[j] = upk2(acc2[rp][j]); }
#pragma unroll
        for (int lane = 0; lane < 2; lane++) {
            int e = rbase + lane;
#pragma unroll
            for (int half = 0; half < 2; half++) {
                int f = n0 + half * 64 + (tx << 2);
                int4   ad = *(const int4*)(AD + (size_t)e * EE + f);
                float4 cc = *(const float4*)(MC + (size_t)e * EE + f);
                int   adr[4] = {ad.x, ad.y, ad.z, ad.w};
                float ccr[4] = {cc.x, cc.y, cc.z, cc.w};
                float outr[4];
#pragma unroll
                for (int j = 0; j < 4; j++) {
                    int jj = half * 4 + j;
                    float s  = (lane ? c[jj].y : c[jj].x) * inv_sq;
                    float sa = (lane ? c2[jj].y : c2[jj].x) * 0.125f;
                    bool merge = (s > thr) && (sa != 0.0f);
                    float co = ccr[j];
                    float r = merge ? (1.0f - co) * s + co * sa : s;
                    if (adr[j] == 0) r = -FLT_MAX;
                    outr[j] = r;
                }
                float4 o = {outr[0], outr[1], outr[2], outr[3]};
                *(float4*)(S + (size_t)e * EE + f) = o;
            }
        }
    }
}

// ---------------------------------------------------------------------------
// Kernel 3: row softmax, one block per row of length 2048.
// ---------------------------------------------------------------------------
__global__ void __launch_bounds__(256) softmax_kernel()
{
    size_t row = blockIdx.x;
    float* S = g_s + row * EE;
    int tid = threadIdx.x;

    float v[8];
    float m = -FLT_MAX;
#pragma unroll
    for (int i = 0; i < 8; i++) {
        v[i] = S[tid + i * 256];
        m = fmaxf(m, v[i]);
    }
    __shared__ float redm[8];
    __shared__ float reds[8];
#pragma unroll
    for (int o = 16; o > 0; o >>= 1) m = fmaxf(m, __shfl_xor_sync(~0u, m, o));
    if ((tid & 31) == 0) redm[tid >> 5] = m;
    __syncthreads();
#pragma unroll
    for (int i = 0; i < 8; i++) m = fmaxf(m, redm[i]);

    float s = 0.f;
#pragma unroll
    for (int i = 0; i < 8; i++) {
        v[i] = __expf(v[i] - m);
        s += v[i];
    }
#pragma unroll
    for (int o = 16; o > 0; o >>= 1) s += __shfl_xor_sync(~0u, s, o);
    if ((tid & 31) == 0) reds[tid >> 5] = s;
    __syncthreads();
    s = 0.f;
#pragma unroll
    for (int i = 0; i < 8; i++) s += reds[i];

    float inv = 1.0f / s;
#pragma unroll
    for (int i = 0; i < 8; i++) S[tid + i * 256] = v[i] * inv;
}

// ---------------------------------------------------------------------------
// Kernel 4: out = attn @ v. grid (4, 16, 8), 256 thr. GEMM-NN K=2048.
// ---------------------------------------------------------------------------
__global__ void __launch_bounds__(256, 2) av_kernel(float* __restrict__ out)
{
    __shared__ __align__(16) float As[2][16][128];
    __shared__ __align__(16) float Bs[2][16][128];

    int b = blockIdx.z;
    int m0 = blockIdx.y * 128, n0 = blockIdx.x * 128;
    float* C = out + (size_t)b * EE * DD;

    ull acc[4][8];
#pragma unroll
    for (int i = 0; i < 4; i++)
#pragma unroll
        for (int j = 0; j < 8; j++) acc[i][j] = 0ull;

    mm_tile<false>(g_s + (size_t)b * EE * EE + (size_t)m0 * EE, EE,
                   g_v + (size_t)b * EE * DD + n0, DD, EE, As, Bs, acc);

    int tx = threadIdx.x & 15, ty = threadIdx.x >> 4;
#pragma unroll
    for (int rp = 0; rp < 4; rp++) {
        int r = m0 + pair_row(rp, ty);
        float2 c[8];
#pragma unroll
        for (int j = 0; j < 8; j++) c[j] = upk2(acc[rp][j]);
        float4 lo0 = {c[0].x, c[1].x, c[2].x, c[3].x};
        float4 lo1 = {c[4].x, c[5].x, c[6].x, c[7].x};
        float4 hi0 = {c[0].y, c[1].y, c[2].y, c[3].y};
        float4 hi1 = {c[4].y, c[5].y, c[6].y, c[7].y};
        *(float4*)(C + (size_t)r * DD + n0 + (tx << 2)) = lo0;
        *(float4*)(C + (size_t)r * DD + n0 + 64 + (tx << 2)) = lo1;
        *(float4*)(C + (size_t)(r + 1) * DD + n0 + (tx << 2)) = hi0;
        *(float4*)(C + (size_t)(r + 1) * DD + n0 + 64 + (tx << 2)) = hi1;
    }
}

// ---------------------------------------------------------------------------
extern "C" void kernel_launch(void* const* d_in, const int* in_sizes, int n_in,
                              void* d_out, int out_size)
{
    const float* x   = (const float*)d_in[0];
    const float* qa  = (const float*)d_in[1];
    const float* ka  = (const float*)d_in[2];
    const int*   adj = (const int*)  d_in[3];
    const float* mc  = (const float*)d_in[4];
    const float* Wq  = (const float*)d_in[5];
    const float* bq  = (const float*)d_in[6];
    const float* Wk  = (const float*)d_in[7];
    const float* bk  = (const float*)d_in[8];
    const float* Wv  = (const float*)d_in[9];
    const float* bv  = (const float*)d_in[10];
    const float* thr = (const float*)d_in[11];

    dim3 blk(256);
    proj_kernel<<<dim3(DD / 128, EE / 128, BB * 3), blk>>>(x, Wq, bq, Wk, bk, Wv, bv);
    scores_kernel<<<dim3(EE / 128, EE / 128, BB), blk>>>(qa, ka, adj, mc, thr);
    softmax_kernel<<<BB * EE, 256>>>();
    av_kernel<<<dim3(DD / 128, EE / 128, BB), blk>>>((float*)d_out);
}